// round 4
// baseline (speedup 1.0000x reference)
#include <cuda_runtime.h>
#include <stdint.h>

// Problem constants (fixed by the reference)
#define NXD   432
#define NYD   496
#define BD    4
#define CD    64
#define PLANE (NXD * NYD)        // 214272
#define NBINS 3
#define NPIL  64000              // B * P_PER per bin

// Total output floats: 3 * 4 * 64 * 214272 = 164,560,896
//   = 41,140,224 float4  = 40176 blocks * 256 threads * 4 float4/thread (exact)
#define TOTAL_F4     41140224
#define ZERO_BLOCKS  40176

// ---------------------------------------------------------------------------
// Kernel 1: zero the entire output. Pure streaming stores, 64B per thread,
// fully contiguous across the block. No loads, no branches.
// ---------------------------------------------------------------------------
__global__ void zero_kernel(float4* __restrict__ out) {
    int t = blockIdx.x * blockDim.x + threadIdx.x;
    float4* p = out + (size_t)t * 4;
    const float4 z = make_float4(0.f, 0.f, 0.f, 0.f);
    p[0] = z;
    p[1] = z;
    p[2] = z;
    p[3] = z;
}

// ---------------------------------------------------------------------------
// Kernel 2: warp-per-pillar scatter. The warp reads the 64-float pillar row
// coalesced (two 128B transactions), then each lane stores channels
// {lane, lane+32} at the pillar's BEV cell (stride PLANE between channels).
// Cells are unique per (bin,b) so no write conflicts with each other; the
// zero_kernel ran earlier on the same stream so ordering is guaranteed.
// ---------------------------------------------------------------------------
__global__ void scatter_kernel(const float* __restrict__ p0, const int* __restrict__ c0,
                               const float* __restrict__ p1, const int* __restrict__ c1,
                               const float* __restrict__ p2, const int* __restrict__ c2,
                               float* __restrict__ out) {
    int gw   = (blockIdx.x * blockDim.x + threadIdx.x) >> 5;  // global warp id
    int lane = threadIdx.x & 31;
    if (gw >= NBINS * NPIL) return;

    int bin = gw / NPIL;
    int p   = gw - bin * NPIL;
    const float* pil = (bin == 0) ? p0 : (bin == 1) ? p1 : p2;
    const int*   cc  = (bin == 0) ? c0 : (bin == 1) ? c1 : c2;

    // coord row [b, z, y, x] — 16B aligned; broadcast load across the warp
    int4 cr = reinterpret_cast<const int4*>(cc)[p];
    int cell = cr.y + cr.z * NXD + cr.w;

    // coalesced pillar-row read: lanes cover channels [0,32) and [32,64)
    const float* row = pil + (size_t)p * CD;
    float v0 = __ldg(row + lane);
    float v1 = __ldg(row + 32 + lane);

    size_t base = ((size_t)(bin * BD + cr.x) * CD) * PLANE + (size_t)cell;
    out[base + (size_t)lane * PLANE]        = v0;
    out[base + (size_t)(lane + 32) * PLANE] = v1;
}

// ---------------------------------------------------------------------------
// Launch. Input order (metadata): pf0, vc0, pf1, vc1, pf2, vc2.
// Output: 3 canvases [4,64,496,432] f32 concatenated.
// ---------------------------------------------------------------------------
extern "C" void kernel_launch(void* const* d_in, const int* in_sizes, int n_in,
                              void* d_out, int out_size) {
    const float* pf0 = (const float*)d_in[0];
    const int*   vc0 = (const int*)  d_in[1];
    const float* pf1 = (const float*)d_in[2];
    const int*   vc1 = (const int*)  d_in[3];
    const float* pf2 = (const float*)d_in[4];
    const int*   vc2 = (const int*)  d_in[5];
    float* out = (float*)d_out;

    // 1) zero the whole output (streaming memset at HBM write BW)
    zero_kernel<<<ZERO_BLOCKS, 256>>>((float4*)out);

    // 2) scatter occupied pillar rows (one warp per pillar)
    {
        int warps   = NBINS * NPIL;              // 192000
        int threads = 256;                       // 8 warps / block
        int blocks  = warps / 8;                 // 24000
        scatter_kernel<<<blocks, threads>>>(pf0, vc0, pf1, vc1, pf2, vc2, out);
    }
}

// round 5
// speedup vs baseline: 3.9766x; 3.9766x over previous
#include <cuda_runtime.h>
#include <stdint.h>

// Problem constants (fixed by the reference)
#define NXD   432
#define NYD   496
#define BD    4
#define CD    64
#define PLANE (NXD * NYD)        // 214272 = 837 * 256 (exact)
#define NBINS 3
#define NPIL  64000              // B * P_PER per bin
#define NBB   (NBINS * BD)       // 12 (bin,b) canvases

// Scratch: pillar-index canvas, -1 = empty. 12 * 214272 * 4B ~= 10.3 MB.
__device__ int g_idx[NBB * PLANE];

// ---------------------------------------------------------------------------
// Kernel 1: fill index canvas with -1 (vectorized int4 stores)
// ---------------------------------------------------------------------------
__global__ void init_idx_kernel() {
    const int n4 = (NBB * PLANE) / 4;   // 642816
    int t = blockIdx.x * blockDim.x + threadIdx.x;
    if (t < n4) {
        reinterpret_cast<int4*>(g_idx)[t] = make_int4(-1, -1, -1, -1);
    }
}

// ---------------------------------------------------------------------------
// Kernel 2: scatter pillar indices into the canvas.
// coords row layout: [b, z, y, x]; local = z + y*NX + x  (nz == 1)
// ---------------------------------------------------------------------------
__global__ void scatter_idx_kernel(const int* __restrict__ c0,
                                   const int* __restrict__ c1,
                                   const int* __restrict__ c2) {
    int t = blockIdx.x * blockDim.x + threadIdx.x;
    if (t >= NBINS * NPIL) return;
    int bin = t / NPIL;
    int p   = t - bin * NPIL;
    const int* cbase = (bin == 0) ? c0 : (bin == 1) ? c1 : c2;
    int4 cr = reinterpret_cast<const int4*>(cbase)[p];   // [b, z, y, x]
    int local = cr.y + cr.z * NXD + cr.w;
    g_idx[(bin * BD + cr.x) * PLANE + local] = p;
}

// ---------------------------------------------------------------------------
// Kernel 3: branch-free gather. One thread per BEV position, all 64 channels.
//  - index load: coalesced 4B (10MB total, L2-resident)
//  - pillar row: 16 x LDG.128 from a clamped pointer. Occupied rows are read
//    exactly once chip-wide (49MB); empty lanes broadcast row 0 (L1 hit).
//  - stores: 64 unconditional warp-coalesced STG.32 (consecutive threads ->
//    consecutive positions -> 128B per instruction). SEL picks value vs 0.
// ---------------------------------------------------------------------------
__global__ void __launch_bounds__(256)
gather_kernel(const float* __restrict__ p0,
              const float* __restrict__ p1,
              const float* __restrict__ p2,
              float* __restrict__ out) {
    int pos = blockIdx.x * 256 + threadIdx.x;  // 0..PLANE-1 (exact cover)
    int bb  = blockIdx.y;                      // 0..11 = bin*4 + b
    int bin = bb >> 2;
    const float* pil = (bin == 0) ? p0 : (bin == 1) ? p1 : p2;

    int idx  = __ldg(g_idx + (size_t)bb * PLANE + pos);
    bool occ = idx >= 0;
    const float4* row =
        reinterpret_cast<const float4*>(pil) + (size_t)(occ ? idx : 0) * (CD / 4);
    float* o = out + (size_t)bb * CD * PLANE + pos;

#pragma unroll
    for (int ch = 0; ch < 4; ch++) {           // 4 chunks of 16 channels
        float4 r[4];
#pragma unroll
        for (int q = 0; q < 4; q++) r[q] = __ldg(row + ch * 4 + q);
#pragma unroll
        for (int q = 0; q < 4; q++) {
            int c = ch * 16 + q * 4;
            o[(size_t)(c + 0) * PLANE] = occ ? r[q].x : 0.f;
            o[(size_t)(c + 1) * PLANE] = occ ? r[q].y : 0.f;
            o[(size_t)(c + 2) * PLANE] = occ ? r[q].z : 0.f;
            o[(size_t)(c + 3) * PLANE] = occ ? r[q].w : 0.f;
        }
    }
}

// ---------------------------------------------------------------------------
// Launch. Input order (metadata): pf0, vc0, pf1, vc1, pf2, vc2.
// Output: 3 canvases [4,64,496,432] f32 concatenated.
// ---------------------------------------------------------------------------
extern "C" void kernel_launch(void* const* d_in, const int* in_sizes, int n_in,
                              void* d_out, int out_size) {
    const float* pf0 = (const float*)d_in[0];
    const int*   vc0 = (const int*)  d_in[1];
    const float* pf1 = (const float*)d_in[2];
    const int*   vc1 = (const int*)  d_in[3];
    const float* pf2 = (const float*)d_in[4];
    const int*   vc2 = (const int*)  d_in[5];
    float* out = (float*)d_out;

    // 1) reset index canvas
    {
        int n4 = (NBB * PLANE) / 4;
        init_idx_kernel<<<(n4 + 255) / 256, 256>>>();
    }
    // 2) scatter pillar indices (tiny)
    {
        int n = NBINS * NPIL;
        scatter_idx_kernel<<<(n + 255) / 256, 256>>>(vc0, vc1, vc2);
    }
    // 3) branch-free gather -> dense output (streaming-store bound)
    {
        dim3 blocks(PLANE / 256, NBB);   // (837, 12)
        gather_kernel<<<blocks, 256>>>(pf0, pf1, pf2, out);
    }
}